// round 15
// baseline (speedup 1.0000x reference)
#include <cuda_runtime.h>
#include <cuda_bf16.h>
#include <cstdint>
#include <float.h>

#define DINL __device__ __forceinline__

// ---------------- scratch (__device__ globals; no allocs allowed) ----------------
__device__ __nv_bfloat16 g_B[128 * 512];        // W^T bf16, [e][k] k-contiguous
__device__ float g_WT[128 * 512];               // W^T fp32, [e][k] (for exact recompute)
__device__ float g_cand[2048 * 128 * 10];       // per-(64-row chunk,e): 5 max + 5 min
__device__ int   g_candIdx[2048 * 128 * 10];    // row-in-batch indices for the above
__device__ float g_pooled[32 * 128];

// ---------------- helpers ----------------
DINL uint32_t smem_u32(const void* p) {
    uint32_t a;
    asm("{ .reg .u64 t; cvta.to.shared.u64 t, %1; cvt.u32.u64 %0, t; }" : "=r"(a) : "l"(p));
    return a;
}

DINL void ldmatrix4(uint32_t& r0, uint32_t& r1, uint32_t& r2, uint32_t& r3, uint32_t addr) {
    asm volatile("ldmatrix.sync.aligned.m8n8.x4.shared.b16 {%0,%1,%2,%3}, [%4];"
                 : "=r"(r0), "=r"(r1), "=r"(r2), "=r"(r3) : "r"(addr));
}

DINL void mma16816(float* c, const uint32_t* a, uint32_t b0, uint32_t b1) {
    asm volatile(
        "mma.sync.aligned.m16n8k16.row.col.f32.bf16.bf16.f32 "
        "{%0,%1,%2,%3}, {%4,%5,%6,%7}, {%8,%9}, {%0,%1,%2,%3};"
        : "+f"(c[0]), "+f"(c[1]), "+f"(c[2]), "+f"(c[3])
        : "r"(a[0]), "r"(a[1]), "r"(a[2]), "r"(a[3]), "r"(b0), "r"(b1));
}

DINL void cp_async16(uint32_t dst, const void* src) {
    asm volatile("cp.async.cg.shared.global [%0], [%1], 16;" :: "r"(dst), "l"(src) : "memory");
}
DINL void cp_commit() { asm volatile("cp.async.commit_group;" ::: "memory"); }
DINL void cp_wait1()  { asm volatile("cp.async.wait_group 1;" ::: "memory"); }

// sorted-5 insertion, max side (v0>=..>=v4)
DINL void ins5max(float v, int i, float& v0, int& i0, float& v1, int& i1,
                  float& v2, int& i2, float& v3, int& i3, float& v4, int& i4) {
    if (v > v4) {
        if (v > v2) {
            if (v > v0)      { v4=v3;i4=i3; v3=v2;i3=i2; v2=v1;i2=i1; v1=v0;i1=i0; v0=v;i0=i; }
            else if (v > v1) { v4=v3;i4=i3; v3=v2;i3=i2; v2=v1;i2=i1; v1=v;i1=i; }
            else             { v4=v3;i4=i3; v3=v2;i3=i2; v2=v;i2=i; }
        } else {
            if (v > v3)      { v4=v3;i4=i3; v3=v;i3=i; }
            else             { v4=v;i4=i; }
        }
    }
}
// sorted-5 insertion, min side (v0<=..<=v4)
DINL void ins5min(float v, int i, float& v0, int& i0, float& v1, int& i1,
                  float& v2, int& i2, float& v3, int& i3, float& v4, int& i4) {
    if (v < v4) {
        if (v < v2) {
            if (v < v0)      { v4=v3;i4=i3; v3=v2;i3=i2; v2=v1;i2=i1; v1=v0;i1=i0; v0=v;i0=i; }
            else if (v < v1) { v4=v3;i4=i3; v3=v2;i3=i2; v2=v1;i2=i1; v1=v;i1=i; }
            else             { v4=v3;i4=i3; v3=v2;i3=i2; v2=v;i2=i; }
        } else {
            if (v < v3)      { v4=v3;i4=i3; v3=v;i3=i; }
            else             { v4=v;i4=i; }
        }
    }
}

// ---------------- kernel 1: W [512,128] fp32 -> g_B bf16 + g_WT fp32 ([e][k]) ----------------
__global__ void prep_B_kernel(const float* __restrict__ W) {
    int idx = blockIdx.x * 256 + threadIdx.x;   // 65536
    int k = idx >> 7, e = idx & 127;
    float v = W[idx];
    g_B[e * 512 + k] = __float2bfloat16(v);
    g_WT[e * 512 + k] = v;
}

// ---------------- kernel 2: 3-CTA/SM bf16 HMMA GEMM (64-row tiles) + top5/bot5 ----------------
// CTA: 64 rows x 128 e. 256 threads, 8 warps, warp tile 32(m) x 32(n) => acc 32 regs.
// K=512 in 16 chunks of 32. Same pipeline skeleton as the R5/R14 champion.
static constexpr int A32_STAGE = 8192;   // 64 rows x 32 k fp32 (128B rows, XOR-swizzled)
static constexpr int A16_STAGE = 4096;   // 64 rows x 32 k bf16 (64B rows, XOR-swizzled)
static constexpr int B_STAGE   = 8192;   // 128 e x 32 k bf16 (64B rows, XOR-swizzled)
static constexpr int OFF_A32 = 0;                             // 3 stages: 0..24576
static constexpr int OFF_A16 = 3 * A32_STAGE;                 // 24576, 2 stages: ..32768
static constexpr int OFF_B   = OFF_A16 + 2 * A16_STAGE;       // 32768, 3 stages: ..57344
static constexpr int SM_BYTES = OFF_B + 3 * B_STAGE;          // 57344 (>= 47104 epilogue)

__global__ void __launch_bounds__(256, 3) gemm_pool_kernel(const float* __restrict__ x) {
    extern __shared__ __align__(128) char smem[];
    const uint32_t sb = smem_u32(smem);
    const int tid = threadIdx.x, lane = tid & 31, wid = tid >> 5;
    const int cta = blockIdx.x;                  // 64-row chunk id (0..2047)
    const float* xg = x + (size_t)cta * 64 * 512;

    // ---- cp.async staging of one K32 chunk (A: 512x16B fp32, B: 512x16B bf16) ----
    #define ISSUE_CHUNK(kc, b3)                                                        \
    {                                                                                  \
        const uint32_t a32 = sb + OFF_A32 + (b3) * A32_STAGE;                          \
        const uint32_t bbb = sb + OFF_B + (b3) * B_STAGE;                              \
        _Pragma("unroll")                                                              \
        for (int i = 0; i < 2; i++) {                                                  \
            int u = tid + 256 * i;                                                     \
            int r = u >> 3, c = u & 7;                                                 \
            uint32_t off = (uint32_t)(r * 128 + ((c ^ (r & 7)) << 4));                 \
            cp_async16(a32 + off, xg + (size_t)r * 512 + (kc) * 32 + c * 4);           \
        }                                                                              \
        _Pragma("unroll")                                                              \
        for (int i = 0; i < 2; i++) {                                                  \
            int u = tid + 256 * i;                                                     \
            int e = u >> 2, c = u & 3;                                                 \
            uint32_t off = (uint32_t)(e * 64 + ((c ^ ((e >> 1) & 3)) << 4));           \
            cp_async16(bbb + off, (const char*)g_B + e * 1024 + (kc) * 64 + c * 16);   \
        }                                                                              \
        cp_commit();                                                                   \
    }

    // ---- convert A32[b3] -> A16[kc&1]: thread owns row r=tid>>2, quarter q=tid&3 ----
    #define CONVERT_A(b3, b2)                                                          \
    {                                                                                  \
        const int r = tid >> 2, qq = tid & 3;                                          \
        const char* src = smem + OFF_A32 + (b3) * A32_STAGE + r * 128;                 \
        char* dst = smem + OFF_A16 + (b2) * A16_STAGE + r * 64;                        \
        uint32_t pk[4];                                                                \
        _Pragma("unroll")                                                              \
        for (int j = 0; j < 2; j++) {                                                  \
            int c = 2 * qq + j;                                                        \
            float4 v = *(const float4*)(src + ((c ^ (r & 7)) << 4));                   \
            __nv_bfloat162 p01 = __floats2bfloat162_rn(v.x, v.y);                      \
            __nv_bfloat162 p23 = __floats2bfloat162_rn(v.z, v.w);                      \
            pk[j * 2] = *(uint32_t*)&p01; pk[j * 2 + 1] = *(uint32_t*)&p23;            \
        }                                                                              \
        uint4 w4; w4.x = pk[0]; w4.y = pk[1]; w4.z = pk[2]; w4.w = pk[3];              \
        *(uint4*)(dst + ((qq ^ ((r >> 1) & 3)) << 4)) = w4;                            \
    }

    // ---- accumulators: warp tile 32(m) x 32(n), fp32 accumulate (32 regs) ----
    const int m0 = (wid & 1) * 32;
    const int n0 = (wid >> 1) * 32;
    float acc[8][4];
    #pragma unroll
    for (int i = 0; i < 8; i++)
        #pragma unroll
        for (int j = 0; j < 4; j++) acc[i][j] = 0.f;

    // prologue: chunks 0, 1 in flight
    ISSUE_CHUNK(0, 0);
    ISSUE_CHUNK(1, 1);

    int b3 = 0;   // kc % 3
    for (int kc = 0; kc < 16; kc++) {
        cp_wait1();          // chunk kc complete (one group may remain in flight)
        __syncthreads();     // publish chunk kc; all threads past MMA(kc-1)

        CONVERT_A(b3, kc & 1);

        int b3n = b3 + 2; if (b3n >= 3) b3n -= 3;
        if (kc + 2 < 16) { ISSUE_CHUNK(kc + 2, b3n); }
        else if (kc + 2 == 16) { cp_commit(); }   // empty group keeps wait accounting

        __syncthreads();     // A16[kc&1] fully written

        const uint32_t Ab = sb + OFF_A16 + (kc & 1) * A16_STAGE;
        const uint32_t Bb = sb + OFF_B + b3 * B_STAGE;
        #pragma unroll
        for (int ks = 0; ks < 2; ks++) {
            const int ch = ks * 2 + (lane >> 4);  // 16B chunk along k
            uint32_t a[2][4];
            #pragma unroll
            for (int mi = 0; mi < 2; mi++) {
                int r = m0 + mi * 16 + (lane & 15);
                uint32_t off = (uint32_t)(r * 64 + ((ch ^ ((r >> 1) & 3)) << 4));
                ldmatrix4(a[mi][0], a[mi][1], a[mi][2], a[mi][3], Ab + off);
            }
            uint32_t bq[2][4];
            #pragma unroll
            for (int nb = 0; nb < 2; nb++) {
                int e = n0 + nb * 16 + (lane & 15);
                uint32_t off = (uint32_t)(e * 64 + ((ch ^ ((e >> 1) & 3)) << 4));
                ldmatrix4(bq[nb][0], bq[nb][1], bq[nb][2], bq[nb][3], Bb + off);
            }
            #pragma unroll
            for (int mi = 0; mi < 2; mi++)
                #pragma unroll
                for (int ni = 0; ni < 4; ni++) {
                    int nb = ni >> 1, h = ni & 1;
                    mma16816(acc[mi * 4 + ni], a[mi], bq[nb][h], bq[nb][h + 2]);
                }
        }

        b3 = (b3 + 1 == 3) ? 0 : b3 + 1;
    }
    __syncthreads();   // all MMA reads done before smem reuse

    // ---- epilogue: acc -> smem f[64][132], then 2x-parallel per-e top5/bot5 scan ----
    float* fb = (float*)smem;
    #pragma unroll
    for (int mi = 0; mi < 2; mi++)
        #pragma unroll
        for (int ni = 0; ni < 4; ni++) {
            int r = m0 + mi * 16 + (lane >> 2);
            int c = n0 + ni * 8 + (lane & 3) * 2;
            float* a4 = acc[mi * 4 + ni];
            fb[r * 132 + c] = a4[0];
            fb[r * 132 + c + 1] = a4[1];
            fb[(r + 8) * 132 + c] = a4[2];
            fb[(r + 8) * 132 + c + 1] = a4[3];
        }
    __syncthreads();

    {
        const int e = tid & 127;
        const int h = tid >> 7;            // 0: rows 0..31, 1: rows 32..63
        float t0=-FLT_MAX,t1=-FLT_MAX,t2=-FLT_MAX,t3=-FLT_MAX,t4=-FLT_MAX;
        int   a0i=0,a1i=0,a2i=0,a3i=0,a4i=0;
        float u0=FLT_MAX,u1=FLT_MAX,u2=FLT_MAX,u3=FLT_MAX,u4=FLT_MAX;
        int   b0i=0,b1i=0,b2i=0,b3i=0,b4i=0;
        const int rbase = (cta & 63) * 64;   // row-in-batch offset (64 chunks/batch)
        for (int r = h * 32; r < h * 32 + 32; r++) {
            float v = fb[r * 132 + e];
            ins5max(v, rbase + r, t0,a0i, t1,a1i, t2,a2i, t3,a3i, t4,a4i);
            ins5min(v, rbase + r, u0,b0i, u1,b1i, u2,b2i, u3,b3i, u4,b4i);
        }
        __syncthreads();
        // scratch region disjoint from fb (fb ends at 33792; scratch at 36864)
        float* sc = (float*)(smem + 36864);
        if (h == 1) {
            float* p = sc + e * 20;
            p[0]=t0; p[1]=t1; p[2]=t2; p[3]=t3; p[4]=t4;
            p[5]=u0; p[6]=u1; p[7]=u2; p[8]=u3; p[9]=u4;
            int* q = (int*)(p + 10);
            q[0]=a0i; q[1]=a1i; q[2]=a2i; q[3]=a3i; q[4]=a4i;
            q[5]=b0i; q[6]=b1i; q[7]=b2i; q[8]=b3i; q[9]=b4i;
        }
        __syncthreads();
        if (h == 0) {
            const float* p = sc + e * 20;
            const int* q = (const int*)(p + 10);
            #pragma unroll
            for (int i = 0; i < 5; i++) {
                ins5max(p[i], q[i], t0,a0i, t1,a1i, t2,a2i, t3,a3i, t4,a4i);
                ins5min(p[5+i], q[5+i], u0,b0i, u1,b1i, u2,b2i, u3,b3i, u4,b4i);
            }
            size_t o = ((size_t)cta * 128 + e) * 10;
            g_cand[o+0]=t0; g_cand[o+1]=t1; g_cand[o+2]=t2; g_cand[o+3]=t3; g_cand[o+4]=t4;
            g_cand[o+5]=u0; g_cand[o+6]=u1; g_cand[o+7]=u2; g_cand[o+8]=u3; g_cand[o+9]=u4;
            g_candIdx[o+0]=a0i; g_candIdx[o+1]=a1i; g_candIdx[o+2]=a2i; g_candIdx[o+3]=a3i; g_candIdx[o+4]=a4i;
            g_candIdx[o+5]=b0i; g_candIdx[o+6]=b1i; g_candIdx[o+7]=b2i; g_candIdx[o+8]=b3i; g_candIdx[o+9]=b4i;
        }
    }
    #undef ISSUE_CHUNK
    #undef CONVERT_A
}

// ---------------- kernel 3: merge chunks, exact fp32 recompute, pool ----------------
// grid = 4096 (b*128+e), block = 64 (warp0: max side, warp1: min side).
// 64 chunks/batch: each lane owns TWO chunks (lane, lane+32); pops head-max per round.
__global__ void merge_pool_kernel(const float* __restrict__ x) {
    const int blk = blockIdx.x;
    const int b = blk >> 7, e = blk & 127;
    const int tid = threadIdx.x, lane = tid & 31, w = tid >> 5;
    __shared__ int s_idx[10];
    __shared__ float s_exact[10];
    __shared__ float s_wcol[512];

    // stage this e's fp32 W column (contiguous in g_WT) into smem
    {
        const float4* wt = (const float4*)(g_WT + (size_t)e * 512);
        ((float4*)s_wcol)[tid] = wt[tid];
        ((float4*)s_wcol)[tid + 64] = wt[tid + 64];
    }

    // phase 1: global top5 over 64 sorted-5 chunk lists (2 lists per lane)
    {
        size_t baseA = (((size_t)(b * 64 + lane)) * 128 + e) * 10 + (w ? 5 : 0);
        size_t baseB = (((size_t)(b * 64 + 32 + lane)) * 128 + e) * 10 + (w ? 5 : 0);
        float va0, va1, va2, va3, va4, vb0, vb1, vb2, vb3, vb4;
        int ja0, ja1, ja2, ja3, ja4, jb0, jb1, jb2, jb3, jb4;
        va0 = g_cand[baseA+0]; va1 = g_cand[baseA+1]; va2 = g_cand[baseA+2];
        va3 = g_cand[baseA+3]; va4 = g_cand[baseA+4];
        ja0 = g_candIdx[baseA+0]; ja1 = g_candIdx[baseA+1]; ja2 = g_candIdx[baseA+2];
        ja3 = g_candIdx[baseA+3]; ja4 = g_candIdx[baseA+4];
        vb0 = g_cand[baseB+0]; vb1 = g_cand[baseB+1]; vb2 = g_cand[baseB+2];
        vb3 = g_cand[baseB+3]; vb4 = g_cand[baseB+4];
        jb0 = g_candIdx[baseB+0]; jb1 = g_candIdx[baseB+1]; jb2 = g_candIdx[baseB+2];
        jb3 = g_candIdx[baseB+3]; jb4 = g_candIdx[baseB+4];
        if (w) {   // min side: negate -> desc keys
            va0 = -va0; va1 = -va1; va2 = -va2; va3 = -va3; va4 = -va4;
            vb0 = -vb0; vb1 = -vb1; vb2 = -vb2; vb3 = -vb3; vb4 = -vb4;
        }

        #pragma unroll
        for (int r = 0; r < 5; r++) {
            bool ta = (va0 >= vb0);
            float head = ta ? va0 : vb0;
            int hidx = ta ? ja0 : jb0;
            float m = head;
            #pragma unroll
            for (int s = 16; s; s >>= 1) m = fmaxf(m, __shfl_xor_sync(0xffffffffu, m, s));
            unsigned ball = __ballot_sync(0xffffffffu, head == m);
            int win = __ffs(ball) - 1;
            int widx = __shfl_sync(0xffffffffu, hidx, win);
            if (lane == 0) s_idx[w * 5 + r] = widx;
            if (lane == win) {
                if (ta) { va0=va1; ja0=ja1; va1=va2; ja1=ja2; va2=va3; ja2=ja3; va3=va4; ja3=ja4; va4=-FLT_MAX; }
                else    { vb0=vb1; jb0=jb1; vb1=vb2; jb1=jb2; vb2=vb3; jb2=jb3; vb3=vb4; jb3=jb4; vb4=-FLT_MAX; }
            }
        }
    }
    __syncthreads();

    // phase 2: exact fp32 dot for each candidate (warp handles its 5), W column from smem
    for (int c = 0; c < 5; c++) {
        int idx = s_idx[w * 5 + c];
        const float* xr = x + ((size_t)b * 4096 + idx) * 512;
        float s = 0.f;
        #pragma unroll
        for (int k = lane; k < 512; k += 32) s = fmaf(xr[k], s_wcol[k], s);
        #pragma unroll
        for (int sh = 16; sh; sh >>= 1) s += __shfl_xor_sync(0xffffffffu, s, sh);
        if (lane == 0) s_exact[w * 5 + c] = s;
    }
    __syncthreads();

    // phase 3: exact top3 + bottom3
    if (tid == 0) {
        float mx[5], mn[5];
        #pragma unroll
        for (int i = 0; i < 5; i++) { mx[i] = s_exact[i]; mn[i] = s_exact[5 + i]; }
        float pmax = 0.f, pmin = 0.f;
        #pragma unroll
        for (int pick = 0; pick < 3; pick++) {
            int bi = 0;
            #pragma unroll
            for (int i = 1; i < 5; i++) if (mx[i] > mx[bi]) bi = i;
            pmax += mx[bi]; mx[bi] = -FLT_MAX;
            int si = 0;
            #pragma unroll
            for (int i = 1; i < 5; i++) if (mn[i] < mn[si]) si = i;
            pmin += mn[si]; mn[si] = FLT_MAX;
        }
        g_pooled[b * 128 + e] = pmax + pmin;
    }
}

// ---------------- kernel 4: L2 normalize ----------------
__global__ void normalize_kernel(float* __restrict__ out) {
    const int b = blockIdx.x, e = threadIdx.x;
    float p = g_pooled[b * 128 + e];
    __shared__ float sq[128];
    sq[e] = p * p;
    __syncthreads();
    for (int s = 64; s; s >>= 1) {
        if (e < s) sq[e] += sq[e + s];
        __syncthreads();
    }
    out[b * 128 + e] = p * rsqrtf(fmaxf(sq[0], 1e-12f));
}

// ---------------- launch ----------------
extern "C" void kernel_launch(void* const* d_in, const int* in_sizes, int n_in,
                              void* d_out, int out_size) {
    (void)in_sizes; (void)n_in; (void)out_size;
    const float* x = (const float*)d_in[0];   // [32,64,64,512] fp32
    const float* W = (const float*)d_in[1];   // [512,128] fp32
    float* out = (float*)d_out;               // [32,128] fp32

    cudaFuncSetAttribute(gemm_pool_kernel,
                         cudaFuncAttributeMaxDynamicSharedMemorySize, SM_BYTES);

    prep_B_kernel<<<256, 256>>>(W);
    gemm_pool_kernel<<<2048, 256, SM_BYTES>>>(x);
    merge_pool_kernel<<<4096, 64>>>(x);
    normalize_kernel<<<32, 128>>>(out);
}